// round 5
// baseline (speedup 1.0000x reference)
#include <cuda_runtime.h>
#include <math.h>

// Problem constants
constexpr int Bc = 4;
constexpr int Sc = 2048;
constexpr int Dc = 1024;
constexpr int Hc = 16;
constexpr int DKc = 64;
constexpr int Mc = Bc * Sc;   // 8192 rows

// Scratch: Q,K,V projected (head layout [B,H,S,DK]) + context
__device__ float g_Q[Mc * Dc];
__device__ float g_K[Mc * Dc];
__device__ float g_V[Mc * Dc];
__device__ float g_C[Mc * Dc];

// ---------------------------------------------------------------------------
// GEMM: Y[m,n] = sum_k X[m,k] * W[n,k] + bias[n]
// in_heads:  X is ctx in [B,H,S,DK] layout (k = h*64+dk)
// out_heads: Y written to [B,H,S,DK] layout (n = h*64+dk)
// Tile: 128x128x16, 256 threads, 8x8 per thread (two 4-wide fragments per dim)
// ---------------------------------------------------------------------------
constexpr int GBK = 16;
constexpr int LDT = 132;   // padded smem leading dim (k-major tiles)

__global__ __launch_bounds__(256, 2) void gemm_nt_kernel(
    const float* __restrict__ X, const float* __restrict__ W,
    const float* __restrict__ bias, float* __restrict__ Y,
    int in_heads, int out_heads)
{
    __shared__ float Xs[GBK * LDT];
    __shared__ float Ws[GBK * LDT];

    const int t = threadIdx.x;
    const int tx = t & 15, ty = t >> 4;
    const int n0 = blockIdx.x * 128;
    const int m0 = blockIdx.y * 128;
    const int lrow = t >> 2;        // 0..63
    const int lk = (t & 3) * 4;     // 0,4,8,12

    float acc[8][8];
#pragma unroll
    for (int i = 0; i < 8; i++)
#pragma unroll
        for (int j = 0; j < 8; j++) acc[i][j] = 0.f;

    for (int k0 = 0; k0 < Dc; k0 += GBK) {
#pragma unroll
        for (int rr = 0; rr < 2; rr++) {
            const int row = lrow + rr * 64;
            const int gk = k0 + lk;
            const int m = m0 + row;
            const float* xsrc;
            if (in_heads) {
                const int bb = m >> 11, ss = m & (Sc - 1);
                const int hh = gk >> 6, cc = gk & 63;
                xsrc = X + (((size_t)(bb * Hc + hh) * Sc + ss) << 6) + cc;
            } else {
                xsrc = X + (size_t)m * Dc + gk;
            }
            const float4 xv = *reinterpret_cast<const float4*>(xsrc);
            Xs[(lk + 0) * LDT + row] = xv.x;
            Xs[(lk + 1) * LDT + row] = xv.y;
            Xs[(lk + 2) * LDT + row] = xv.z;
            Xs[(lk + 3) * LDT + row] = xv.w;

            const float4 wv =
                *reinterpret_cast<const float4*>(W + (size_t)(n0 + row) * Dc + gk);
            Ws[(lk + 0) * LDT + row] = wv.x;
            Ws[(lk + 1) * LDT + row] = wv.y;
            Ws[(lk + 2) * LDT + row] = wv.z;
            Ws[(lk + 3) * LDT + row] = wv.w;
        }
        __syncthreads();

#pragma unroll
        for (int kk = 0; kk < GBK; kk++) {
            const float4 a0 = *reinterpret_cast<const float4*>(&Xs[kk * LDT + ty * 4]);
            const float4 a1 = *reinterpret_cast<const float4*>(&Xs[kk * LDT + 64 + ty * 4]);
            const float4 b0 = *reinterpret_cast<const float4*>(&Ws[kk * LDT + tx * 4]);
            const float4 b1 = *reinterpret_cast<const float4*>(&Ws[kk * LDT + 64 + tx * 4]);
            const float av[8] = {a0.x, a0.y, a0.z, a0.w, a1.x, a1.y, a1.z, a1.w};
            const float bv[8] = {b0.x, b0.y, b0.z, b0.w, b1.x, b1.y, b1.z, b1.w};
#pragma unroll
            for (int i = 0; i < 8; i++)
#pragma unroll
                for (int j = 0; j < 8; j++)
                    acc[i][j] = fmaf(av[i], bv[j], acc[i][j]);
        }
        __syncthreads();
    }

#pragma unroll
    for (int ri = 0; ri < 2; ri++)
#pragma unroll
    for (int i = 0; i < 4; i++) {
        const int m = m0 + ri * 64 + ty * 4 + i;
#pragma unroll
        for (int cj = 0; cj < 2; cj++) {
            const int n = n0 + cj * 64 + tx * 4;
            float4 r;
            r.x = acc[ri * 4 + i][cj * 4 + 0] + __ldg(bias + n + 0);
            r.y = acc[ri * 4 + i][cj * 4 + 1] + __ldg(bias + n + 1);
            r.z = acc[ri * 4 + i][cj * 4 + 2] + __ldg(bias + n + 2);
            r.w = acc[ri * 4 + i][cj * 4 + 3] + __ldg(bias + n + 3);
            if (out_heads) {
                const int bb = m >> 11, ss = m & (Sc - 1);
                const int hh = n >> 6, cc = n & 63;
                *reinterpret_cast<float4*>(
                    Y + (((size_t)(bb * Hc + hh) * Sc + ss) << 6) + cc) = r;
            } else {
                *reinterpret_cast<float4*>(Y + (size_t)m * Dc + n) = r;
            }
        }
    }
}

// ---------------------------------------------------------------------------
// Flash attention, fp32. CTA = (q-tile of 64) x head x batch. 256 threads.
// S tile 64x64: thread (ty,tx) owns rows ty*4..+3, cols tx*4..+3.
// K stored transposed (d-major, padded ld=68) for conflict-free LDS.128.
// ---------------------------------------------------------------------------
constexpr int KLD = 68;
constexpr int ATTN_SMEM =
    (64 * 64 /*Q*/ + 64 * KLD /*Kt*/ + 64 * 64 /*V*/ + 64 * 64 /*P*/) * 4;

__global__ __launch_bounds__(256) void attn_kernel(const int* __restrict__ mask)
{
    extern __shared__ float sm[];
    float* Qs  = sm;                   // [64][64]
    float* Kst = Qs + 64 * 64;         // [64 d][KLD]
    float* Vs  = Kst + 64 * KLD;       // [64][64]
    float* Ps  = Vs + 64 * 64;         // [64][64]

    const int t = threadIdx.x;
    const int tx = t & 15, ty = t >> 4;
    const int q0 = blockIdx.x * 64;
    const int h = blockIdx.y;
    const int b = blockIdx.z;

    const float* Qg    = g_Q + ((size_t)(b * Hc + h) * Sc + q0) * DKc;
    const float* Kbase = g_K + (size_t)(b * Hc + h) * Sc * DKc;
    const float* Vbase = g_V + (size_t)(b * Hc + h) * Sc * DKc;

#pragma unroll
    for (int w = 0; w < 4; w++) {
        const int f = w * 256 + t;  // float4 index 0..1023
        reinterpret_cast<float4*>(Qs)[f] = reinterpret_cast<const float4*>(Qg)[f];
    }

    float mrow[4], lrow[4], o[4][4];
#pragma unroll
    for (int i = 0; i < 4; i++) {
        mrow[i] = -INFINITY; lrow[i] = 0.f;
#pragma unroll
        for (int j = 0; j < 4; j++) o[i][j] = 0.f;
    }

    for (int j0 = 0; j0 < Sc; j0 += 64) {
        // Load K tile transposed: Kst[d][c] = K[j0+c][d]
        const float* Kg = Kbase + (size_t)j0 * DKc;
#pragma unroll
        for (int w = 0; w < 4; w++) {
            const int f = w * 256 + t;
            const int c = f >> 4;        // key row 0..63
            const int dblk = f & 15;
            const float4 kv = reinterpret_cast<const float4*>(Kg)[f];
            Kst[(dblk * 4 + 0) * KLD + c] = kv.x;
            Kst[(dblk * 4 + 1) * KLD + c] = kv.y;
            Kst[(dblk * 4 + 2) * KLD + c] = kv.z;
            Kst[(dblk * 4 + 3) * KLD + c] = kv.w;
        }
        // Load V tile natural layout
        const float* Vg = Vbase + (size_t)j0 * DKc;
#pragma unroll
        for (int w = 0; w < 4; w++) {
            const int f = w * 256 + t;
            reinterpret_cast<float4*>(Vs)[f] = reinterpret_cast<const float4*>(Vg)[f];
        }
        __syncthreads();

        // S = Q K^T
        float s[4][4];
#pragma unroll
        for (int i = 0; i < 4; i++)
#pragma unroll
            for (int j = 0; j < 4; j++) s[i][j] = 0.f;

#pragma unroll 4
        for (int dblk = 0; dblk < 16; dblk++) {
            float qa[4][4];
#pragma unroll
            for (int i = 0; i < 4; i++) {
                const float4 qv =
                    *reinterpret_cast<const float4*>(&Qs[(ty * 4 + i) * 64 + dblk * 4]);
                qa[i][0] = qv.x; qa[i][1] = qv.y; qa[i][2] = qv.z; qa[i][3] = qv.w;
            }
#pragma unroll
            for (int u = 0; u < 4; u++) {
                const float4 kv = *reinterpret_cast<const float4*>(
                    &Kst[(dblk * 4 + u) * KLD + tx * 4]);
                const float kb[4] = {kv.x, kv.y, kv.z, kv.w};
#pragma unroll
                for (int i = 0; i < 4; i++)
#pragma unroll
                    for (int j = 0; j < 4; j++)
                        s[i][j] = fmaf(qa[i][u], kb[j], s[i][j]);
            }
        }

        // Mask + online softmax
#pragma unroll
        for (int i = 0; i < 4; i++) {
            const int q = q0 + ty * 4 + i;
            const int4 mv = *reinterpret_cast<const int4*>(
                mask + ((size_t)b * Sc + q) * Sc + j0 + tx * 4);
            float sv[4];
            sv[0] = mv.x ? s[i][0] * 0.125f : -1e9f;
            sv[1] = mv.y ? s[i][1] * 0.125f : -1e9f;
            sv[2] = mv.z ? s[i][2] * 0.125f : -1e9f;
            sv[3] = mv.w ? s[i][3] * 0.125f : -1e9f;
            float rm = fmaxf(fmaxf(sv[0], sv[1]), fmaxf(sv[2], sv[3]));
#pragma unroll
            for (int msk = 8; msk >= 1; msk >>= 1)
                rm = fmaxf(rm, __shfl_xor_sync(0xffffffffu, rm, msk));
            const float mnew = fmaxf(mrow[i], rm);
            const float corr = __expf(mrow[i] - mnew);
            float p[4];
            float rs = 0.f;
#pragma unroll
            for (int j = 0; j < 4; j++) { p[j] = __expf(sv[j] - mnew); rs += p[j]; }
#pragma unroll
            for (int msk = 8; msk >= 1; msk >>= 1)
                rs += __shfl_xor_sync(0xffffffffu, rs, msk);
            lrow[i] = lrow[i] * corr + rs;
            mrow[i] = mnew;
#pragma unroll
            for (int j = 0; j < 4; j++) o[i][j] *= corr;
            *reinterpret_cast<float4*>(&Ps[(ty * 4 + i) * 64 + tx * 4]) =
                make_float4(p[0], p[1], p[2], p[3]);
        }
        __syncthreads();

        // O += P V
#pragma unroll 4
        for (int kblk = 0; kblk < 16; kblk++) {
            float pa[4][4];
#pragma unroll
            for (int i = 0; i < 4; i++) {
                const float4 pv =
                    *reinterpret_cast<const float4*>(&Ps[(ty * 4 + i) * 64 + kblk * 4]);
                pa[i][0] = pv.x; pa[i][1] = pv.y; pa[i][2] = pv.z; pa[i][3] = pv.w;
            }
#pragma unroll
            for (int u = 0; u < 4; u++) {
                const float4 vv = *reinterpret_cast<const float4*>(
                    &Vs[(kblk * 4 + u) * 64 + tx * 4]);
                const float vb[4] = {vv.x, vv.y, vv.z, vv.w};
#pragma unroll
                for (int i = 0; i < 4; i++)
#pragma unroll
                    for (int j = 0; j < 4; j++)
                        o[i][j] = fmaf(pa[i][u], vb[j], o[i][j]);
            }
        }
        __syncthreads();
    }

    float* Cg = g_C + ((size_t)(b * Hc + h) * Sc + q0) * DKc;
#pragma unroll
    for (int i = 0; i < 4; i++) {
        const float inv = 1.f / lrow[i];
        *reinterpret_cast<float4*>(Cg + (ty * 4 + i) * 64 + tx * 4) =
            make_float4(o[i][0] * inv, o[i][1] * inv, o[i][2] * inv, o[i][3] * inv);
    }
}

// ---------------------------------------------------------------------------
// Launch
// ---------------------------------------------------------------------------
extern "C" void kernel_launch(void* const* d_in, const int* in_sizes, int n_in,
                              void* d_out, int out_size)
{
    const float* query = (const float*)d_in[0];
    const float* key   = (const float*)d_in[1];
    const float* value = (const float*)d_in[2];
    const int*   mask  = (const int*)d_in[3];
    const float* Wq = (const float*)d_in[4];
    const float* bq = (const float*)d_in[5];
    const float* Wk = (const float*)d_in[6];
    const float* bk = (const float*)d_in[7];
    const float* Wv = (const float*)d_in[8];
    const float* bv = (const float*)d_in[9];
    const float* Wo = (const float*)d_in[10];
    const float* bo = (const float*)d_in[11];
    float* out = (float*)d_out;

    float *pQ, *pK, *pV, *pC;
    cudaGetSymbolAddress((void**)&pQ, g_Q);
    cudaGetSymbolAddress((void**)&pK, g_K);
    cudaGetSymbolAddress((void**)&pV, g_V);
    cudaGetSymbolAddress((void**)&pC, g_C);

    cudaFuncSetAttribute(attn_kernel,
                         cudaFuncAttributeMaxDynamicSharedMemorySize, ATTN_SMEM);

    const dim3 gg(Dc / 128, Mc / 128);
    gemm_nt_kernel<<<gg, 256>>>(query, Wq, bq, pQ, 0, 1);
    gemm_nt_kernel<<<gg, 256>>>(key,   Wk, bk, pK, 0, 1);
    gemm_nt_kernel<<<gg, 256>>>(value, Wv, bv, pV, 0, 1);
    attn_kernel<<<dim3(Sc / 64, Hc, Bc), 256, ATTN_SMEM>>>(mask);
    gemm_nt_kernel<<<gg, 256>>>(pC, Wo, bo, out, 1, 0);
}

// round 7
// speedup vs baseline: 2.7696x; 2.7696x over previous
#include <cuda_runtime.h>
#include <cuda_bf16.h>
#include <math.h>
#include <stdint.h>

constexpr int Bc = 4;
constexpr int Sc = 2048;
constexpr int Dc = 1024;
constexpr int Hc = 16;
constexpr int DKc = 64;
constexpr int Mc = Bc * Sc;   // 8192

// bf16 split buffers (hi/lo)
__device__ __nv_bfloat16 g_Qh[Mc * Dc], g_Ql[Mc * Dc];
__device__ __nv_bfloat16 g_Kh[Mc * Dc], g_Kl[Mc * Dc];
__device__ __nv_bfloat16 g_Vh[Mc * Dc], g_Vl[Mc * Dc];
__device__ __nv_bfloat16 g_Xh[Mc * Dc], g_Xl[Mc * Dc];  // gemm input / ctx split
__device__ __nv_bfloat16 g_Wh[Dc * Dc], g_Wl[Dc * Dc];  // weight split (reused)

// ---------------------------------------------------------------------------
// Helpers
// ---------------------------------------------------------------------------
__device__ __forceinline__ uint32_t smem_u32(const void* p) {
    return (uint32_t)__cvta_generic_to_shared(p);
}
__device__ __forceinline__ void cp16(uint32_t dst, const void* src) {
    asm volatile("cp.async.cg.shared.global [%0], [%1], 16;" :: "r"(dst), "l"(src));
}
__device__ __forceinline__ void cp_commit() { asm volatile("cp.async.commit_group;"); }
template<int N> __device__ __forceinline__ void cp_wait() {
    asm volatile("cp.async.wait_group %0;" :: "n"(N));
}
__device__ __forceinline__ void ldsm4(uint32_t* r, uint32_t a) {
    asm volatile("ldmatrix.sync.aligned.m8n8.x4.shared.b16 {%0,%1,%2,%3}, [%4];"
        : "=r"(r[0]), "=r"(r[1]), "=r"(r[2]), "=r"(r[3]) : "r"(a));
}
__device__ __forceinline__ void ldsm4t(uint32_t* r, uint32_t a) {
    asm volatile("ldmatrix.sync.aligned.m8n8.x4.trans.shared.b16 {%0,%1,%2,%3}, [%4];"
        : "=r"(r[0]), "=r"(r[1]), "=r"(r[2]), "=r"(r[3]) : "r"(a));
}
__device__ __forceinline__ void mma16816(float* c, const uint32_t* a, const uint32_t* b) {
    asm volatile(
        "mma.sync.aligned.m16n8k16.row.col.f32.bf16.bf16.f32 "
        "{%0,%1,%2,%3}, {%4,%5,%6,%7}, {%8,%9}, {%0,%1,%2,%3};"
        : "+f"(c[0]), "+f"(c[1]), "+f"(c[2]), "+f"(c[3])
        : "r"(a[0]), "r"(a[1]), "r"(a[2]), "r"(a[3]), "r"(b[0]), "r"(b[1]));
}
// split (a,b) into packed bf16x2 hi + lo (residual). low 16 bits = a (even col).
__device__ __forceinline__ uint32_t split_pack(float a, float b, uint32_t& lo) {
    __nv_bfloat16 ha = __float2bfloat16(a), hb = __float2bfloat16(b);
    float ra = a - __bfloat162float(ha), rb = b - __bfloat162float(hb);
    __nv_bfloat16 la = __float2bfloat16(ra), lb = __float2bfloat16(rb);
    lo = ((uint32_t)__bfloat16_as_ushort(lb) << 16) | __bfloat16_as_ushort(la);
    return ((uint32_t)__bfloat16_as_ushort(hb) << 16) | __bfloat16_as_ushort(ha);
}
// swizzled byte offset within a tile of 128B rows (8 x 16B chunks per row)
__device__ __forceinline__ uint32_t swz(int row, int chunk) {
    return (uint32_t)((row << 7) + ((chunk ^ (row & 7)) << 4));
}

// ---------------------------------------------------------------------------
// fp32 -> bf16 hi/lo split (inputs & weights)
// ---------------------------------------------------------------------------
__global__ __launch_bounds__(256) void split_kernel(
    const float* __restrict__ x, __nv_bfloat16* __restrict__ hi,
    __nv_bfloat16* __restrict__ lo, int n4)
{
    int i = blockIdx.x * blockDim.x + threadIdx.x;
    if (i >= n4) return;
    float4 v = reinterpret_cast<const float4*>(x)[i];
    uint32_t l0, l1;
    uint32_t h0 = split_pack(v.x, v.y, l0);
    uint32_t h1 = split_pack(v.z, v.w, l1);
    uint2 H = {h0, h1}, L = {l0, l1};
    reinterpret_cast<uint2*>(hi)[i] = H;
    reinterpret_cast<uint2*>(lo)[i] = L;
}

// ---------------------------------------------------------------------------
// Split-bf16 GEMM on HMMA:  Y[m,n] = sum_k A[m,k]*B[n,k] + bias[n]
// D = Ah*Bh + Ah*Bl + Al*Bh.  Tile 128x128, k-chunk 64, 2-stage cp.async.
// mode 0: fp32 flat out.  mode 1: bf16 hi/lo out, head layout, *scale.
// ---------------------------------------------------------------------------
constexpr int GSTAGE = 65536;
constexpr int GEMM_SMEM = 2 * GSTAGE;

__global__ __launch_bounds__(256) void gemm_bf16(
    const __nv_bfloat16* __restrict__ Ah, const __nv_bfloat16* __restrict__ Al,
    const __nv_bfloat16* __restrict__ Bh, const __nv_bfloat16* __restrict__ Bl,
    const float* __restrict__ bias, float scale,
    float* __restrict__ Yf, __nv_bfloat16* __restrict__ Yh,
    __nv_bfloat16* __restrict__ Yl, int mode)
{
    extern __shared__ char smem[];
    const uint32_t sb = smem_u32(smem);
    const int t = threadIdx.x, wid = t >> 5, l = t & 31;
    const int g = l >> 2, tq = l & 3;
    const int n0 = blockIdx.x * 128, m0 = blockIdx.y * 128;
    const int mrow = (wid & 1) * 64, ncol = (wid >> 1) * 32;

    auto ld_stage = [&](int c, int s) {
        const uint32_t st = sb + (uint32_t)s * GSTAGE;
#pragma unroll
        for (int rep = 0; rep < 4; rep++) {
            const int id = t + 256 * rep;
            const int row = id >> 3, ch = id & 7;
            const int gk = c * 64 + ch * 8;
            const uint32_t d = swz(row, ch);
            cp16(st + d,          Ah + (size_t)(m0 + row) * Dc + gk);
            cp16(st + 16384 + d,  Al + (size_t)(m0 + row) * Dc + gk);
            cp16(st + 32768 + d,  Bh + (size_t)(n0 + row) * Dc + gk);
            cp16(st + 49152 + d,  Bl + (size_t)(n0 + row) * Dc + gk);
        }
    };

    float acc[4][4][4];
#pragma unroll
    for (int i = 0; i < 4; i++)
#pragma unroll
        for (int j = 0; j < 4; j++)
#pragma unroll
            for (int k = 0; k < 4; k++) acc[i][j][k] = 0.f;

    ld_stage(0, 0); cp_commit();
    ld_stage(1, 1); cp_commit();
    cp_wait<1>(); __syncthreads();

    const int arow = mrow + (l & 15);
    const int acs = l >> 4;
    const int brow = ncol + ((l >> 4) << 3) + (l & 7);
    const int bcs = (l >> 3) & 1;

    for (int c = 0; c < 16; c++) {
        const uint32_t st = sb + (uint32_t)(c & 1) * GSTAGE;
#pragma unroll
        for (int ks = 0; ks < 4; ks++) {
            uint32_t bH[2][4], bL[2][4];
#pragma unroll
            for (int jp = 0; jp < 2; jp++) {
                const int br = brow + jp * 16;
                const uint32_t ad = swz(br, ks * 2 + bcs);
                ldsm4(bH[jp], st + 32768 + ad);
                ldsm4(bL[jp], st + 49152 + ad);
            }
#pragma unroll
            for (int i = 0; i < 4; i++) {
                const int ar = arow + 16 * i;
                const uint32_t ad = swz(ar, ks * 2 + acs);
                uint32_t aH[4], aL[4];
                ldsm4(aH, st + ad);
                ldsm4(aL, st + 16384 + ad);
#pragma unroll
                for (int jp = 0; jp < 2; jp++) {
                    mma16816(acc[i][2 * jp], aH, &bH[jp][0]);
                    mma16816(acc[i][2 * jp], aH, &bL[jp][0]);
                    mma16816(acc[i][2 * jp], aL, &bH[jp][0]);
                    mma16816(acc[i][2 * jp + 1], aH, &bH[jp][2]);
                    mma16816(acc[i][2 * jp + 1], aH, &bL[jp][2]);
                    mma16816(acc[i][2 * jp + 1], aL, &bH[jp][2]);
                }
            }
        }
        __syncthreads();
        if (c + 2 < 16) { ld_stage(c + 2, c & 1); cp_commit(); cp_wait<1>(); }
        else cp_wait<0>();
        __syncthreads();
    }

    // Epilogue
#pragma unroll
    for (int i = 0; i < 4; i++) {
        const int m1 = m0 + mrow + 16 * i + g;
        const int m2 = m1 + 8;
#pragma unroll
        for (int j = 0; j < 4; j++) {
            const int nc = n0 + ncol + 8 * j + 2 * tq;
            const float2 bb = *reinterpret_cast<const float2*>(bias + nc);
            float v00 = acc[i][j][0] + bb.x, v01 = acc[i][j][1] + bb.y;
            float v10 = acc[i][j][2] + bb.x, v11 = acc[i][j][3] + bb.y;
            if (mode == 0) {
                float2 r0 = {v00, v01}, r1 = {v10, v11};
                *reinterpret_cast<float2*>(Yf + (size_t)m1 * Dc + nc) = r0;
                *reinterpret_cast<float2*>(Yf + (size_t)m2 * Dc + nc) = r1;
            } else {
                v00 *= scale; v01 *= scale; v10 *= scale; v11 *= scale;
                const int hh = nc >> 6, cc = nc & 63;
                uint32_t lo;
                {
                    const int bb2 = m1 >> 11, ss = m1 & (Sc - 1);
                    const size_t idx = (((size_t)(bb2 * Hc + hh) * Sc + ss) << 6) + cc;
                    uint32_t hi = split_pack(v00, v01, lo);
                    *reinterpret_cast<uint32_t*>(Yh + idx) = hi;
                    *reinterpret_cast<uint32_t*>(Yl + idx) = lo;
                }
                {
                    const int bb2 = m2 >> 11, ss = m2 & (Sc - 1);
                    const size_t idx = (((size_t)(bb2 * Hc + hh) * Sc + ss) << 6) + cc;
                    uint32_t hi = split_pack(v10, v11, lo);
                    *reinterpret_cast<uint32_t*>(Yh + idx) = hi;
                    *reinterpret_cast<uint32_t*>(Yl + idx) = lo;
                }
            }
        }
    }
}

// ---------------------------------------------------------------------------
// Flash attention on HMMA.  CTA: 64 q-rows x (head,batch). 128 threads.
// QK^T: Qh*Kh + Qh*Kl + Ql*Kh (Q pre-scaled by 1/8).
// P*V : Ph*Vh + Ph*Vl + Pl*Vh.
// smem: Qh/Ql (8KB each) + 2 stages x (Kh,Kl,Vh,Vl; 8KB each) = 80KB.
// ---------------------------------------------------------------------------
constexpr int ATTN_SMEM = 16384 + 2 * 32768;

__global__ __launch_bounds__(128) void attn_hmma(const int* __restrict__ mask)
{
    extern __shared__ char smem[];
    const uint32_t sb = smem_u32(smem);
    const int t = threadIdx.x, w = t >> 5, l = t & 31;
    const int g = l >> 2, tq = l & 3;
    const int q0 = blockIdx.x * 64;
    const int h = blockIdx.y, b = blockIdx.z;

    const size_t hb = (size_t)(b * Hc + h) * Sc * DKc;
    const __nv_bfloat16* Qhg = g_Qh + hb + (size_t)q0 * DKc;
    const __nv_bfloat16* Qlg = g_Ql + hb + (size_t)q0 * DKc;
    const __nv_bfloat16* Khg = g_Kh + hb;
    const __nv_bfloat16* Klg = g_Kl + hb;
    const __nv_bfloat16* Vhg = g_Vh + hb;
    const __nv_bfloat16* Vlg = g_Vl + hb;

    const uint32_t QH = sb, QL = sb + 8192;

    auto ld_kv = [&](int jb, int s) {
        const uint32_t st = sb + 16384 + (uint32_t)s * 32768;
        const int k0 = jb * 64;
#pragma unroll
        for (int rep = 0; rep < 4; rep++) {
            const int id = t + 128 * rep;
            const int row = id >> 3, ch = id & 7;
            const size_t off = (size_t)(k0 + row) * DKc + ch * 8;
            const uint32_t d = swz(row, ch);
            cp16(st + d,          Khg + off);
            cp16(st + 8192 + d,   Klg + off);
            cp16(st + 16384 + d,  Vhg + off);
            cp16(st + 24576 + d,  Vlg + off);
        }
    };

    // Q load + first KV stage in group 0
    {
#pragma unroll
        for (int rep = 0; rep < 4; rep++) {
            const int id = t + 128 * rep;
            const int row = id >> 3, ch = id & 7;
            const size_t off = (size_t)row * DKc + ch * 8;
            const uint32_t d = swz(row, ch);
            cp16(QH + d, Qhg + off);
            cp16(QL + d, Qlg + off);
        }
        ld_kv(0, 0); cp_commit();
        ld_kv(1, 1); cp_commit();
        cp_wait<1>(); __syncthreads();
    }

    float o[8][4];
#pragma unroll
    for (int j = 0; j < 8; j++)
#pragma unroll
        for (int k = 0; k < 4; k++) o[j][k] = 0.f;
    float m0 = -INFINITY, m1 = -INFINITY, l0 = 0.f, l1 = 0.f;

    const int qrow = q0 + 16 * w + g;
    const int* mrow0 = mask + ((size_t)b * Sc + qrow) * Sc;
    const int* mrow1 = mrow0 + 8 * Sc;

    const int arow = 16 * w + (l & 15);
    const int acs = l >> 4;
    const int brlo = ((l >> 4) << 3) + (l & 7);
    const int bcs = (l >> 3) & 1;
    const int vrlo = ((l >> 3) & 1) * 8 + (l & 7);
    const int vcs = (l >> 4) & 1;

    for (int jb = 0; jb < 32; jb++) {
        const uint32_t st = sb + 16384 + (uint32_t)(jb & 1) * 32768;
        const int k0 = jb * 64;

        // --- S = Q K^T (split) ---
        float sfr[8][4];
#pragma unroll
        for (int j = 0; j < 8; j++)
#pragma unroll
            for (int k = 0; k < 4; k++) sfr[j][k] = 0.f;

#pragma unroll
        for (int ks = 0; ks < 4; ks++) {
            uint32_t aH[4], aL[4];
            const uint32_t ad = swz(arow, ks * 2 + acs);
            ldsm4(aH, QH + ad);
            ldsm4(aL, QL + ad);
#pragma unroll
            for (int jp = 0; jp < 4; jp++) {
                uint32_t bH[4], bL[4];
                const uint32_t bd = swz(16 * jp + brlo, ks * 2 + bcs);
                ldsm4(bH, st + bd);
                ldsm4(bL, st + 8192 + bd);
                mma16816(sfr[2 * jp], aH, &bH[0]);
                mma16816(sfr[2 * jp], aH, &bL[0]);
                mma16816(sfr[2 * jp], aL, &bH[0]);
                mma16816(sfr[2 * jp + 1], aH, &bH[2]);
                mma16816(sfr[2 * jp + 1], aH, &bL[2]);
                mma16816(sfr[2 * jp + 1], aL, &bH[2]);
            }
        }

        // --- mask + online softmax ---
#pragma unroll
        for (int j = 0; j < 8; j++) {
            const int2 mv0 = *reinterpret_cast<const int2*>(mrow0 + k0 + 8 * j + 2 * tq);
            const int2 mv1 = *reinterpret_cast<const int2*>(mrow1 + k0 + 8 * j + 2 * tq);
            sfr[j][0] = mv0.x ? sfr[j][0] : -1e9f;
            sfr[j][1] = mv0.y ? sfr[j][1] : -1e9f;
            sfr[j][2] = mv1.x ? sfr[j][2] : -1e9f;
            sfr[j][3] = mv1.y ? sfr[j][3] : -1e9f;
        }
        float mx0 = -INFINITY, mx1 = -INFINITY;
#pragma unroll
        for (int j = 0; j < 8; j++) {
            mx0 = fmaxf(mx0, fmaxf(sfr[j][0], sfr[j][1]));
            mx1 = fmaxf(mx1, fmaxf(sfr[j][2], sfr[j][3]));
        }
        mx0 = fmaxf(mx0, __shfl_xor_sync(0xffffffffu, mx0, 1));
        mx0 = fmaxf(mx0, __shfl_xor_sync(0xffffffffu, mx0, 2));
        mx1 = fmaxf(mx1, __shfl_xor_sync(0xffffffffu, mx1, 1));
        mx1 = fmaxf(mx1, __shfl_xor_sync(0xffffffffu, mx1, 2));
        const float mn0 = fmaxf(m0, mx0), mn1 = fmaxf(m1, mx1);
        const float cr0 = __expf(m0 - mn0), cr1 = __expf(m1 - mn1);
        float s0 = 0.f, s1 = 0.f;
#pragma unroll
        for (int j = 0; j < 8; j++) {
            sfr[j][0] = __expf(sfr[j][0] - mn0); s0 += sfr[j][0];
            sfr[j][1] = __expf(sfr[j][1] - mn0); s0 += sfr[j][1];
            sfr[j][2] = __expf(sfr[j][2] - mn1); s1 += sfr[j][2];
            sfr[j][3] = __expf(sfr[j][3] - mn1); s1 += sfr[j][3];
        }
        s0 += __shfl_xor_sync(0xffffffffu, s0, 1);
        s0 += __shfl_xor_sync(0xffffffffu, s0, 2);
        s1 += __shfl_xor_sync(0xffffffffu, s1, 1);
        s1 += __shfl_xor_sync(0xffffffffu, s1, 2);
        l0 = l0 * cr0 + s0;  m0 = mn0;
        l1 = l1 * cr1 + s1;  m1 = mn1;
#pragma unroll
        for (int j = 0; j < 8; j++) {
            o[j][0] *= cr0; o[j][1] *= cr0; o[j][2] *= cr1; o[j][3] *= cr1;
        }

        // --- O += P V (split) ---
#pragma unroll
        for (int ks = 0; ks < 4; ks++) {
            uint32_t aPh[4], aPl[4];
            aPh[0] = split_pack(sfr[2 * ks][0],     sfr[2 * ks][1],     aPl[0]);
            aPh[1] = split_pack(sfr[2 * ks][2],     sfr[2 * ks][3],     aPl[1]);
            aPh[2] = split_pack(sfr[2 * ks + 1][0], sfr[2 * ks + 1][1], aPl[2]);
            aPh[3] = split_pack(sfr[2 * ks + 1][2], sfr[2 * ks + 1][3], aPl[3]);
#pragma unroll
            for (int jp = 0; jp < 4; jp++) {
                uint32_t vH[4], vL[4];
                const uint32_t vd = swz(16 * ks + vrlo, 2 * jp + vcs);
                ldsm4t(vH, st + 16384 + vd);
                ldsm4t(vL, st + 24576 + vd);
                mma16816(o[2 * jp], aPh, &vH[0]);
                mma16816(o[2 * jp], aPh, &vL[0]);
                mma16816(o[2 * jp], aPl, &vH[0]);
                mma16816(o[2 * jp + 1], aPh, &vH[2]);
                mma16816(o[2 * jp + 1], aPh, &vL[2]);
                mma16816(o[2 * jp + 1], aPl, &vH[2]);
            }
        }

        __syncthreads();
        if (jb + 2 < 32) { ld_kv(jb + 2, jb & 1); cp_commit(); cp_wait<1>(); }
        else cp_wait<0>();
        __syncthreads();
    }

    // Epilogue: ctx written pre-split, flat [B*S, D]
    const float i0 = 1.f / l0, i1 = 1.f / l1;
    const size_t r0 = (size_t)(b * Sc + qrow) * Dc + h * DKc;
    const size_t r1 = r0 + 8 * Dc;
#pragma unroll
    for (int j = 0; j < 8; j++) {
        const int cc = 8 * j + 2 * tq;
        uint32_t lo;
        uint32_t hi = split_pack(o[j][0] * i0, o[j][1] * i0, lo);
        *reinterpret_cast<uint32_t*>(g_Xh + r0 + cc) = hi;
        *reinterpret_cast<uint32_t*>(g_Xl + r0 + cc) = lo;
        hi = split_pack(o[j][2] * i1, o[j][3] * i1, lo);
        *reinterpret_cast<uint32_t*>(g_Xh + r1 + cc) = hi;
        *reinterpret_cast<uint32_t*>(g_Xl + r1 + cc) = lo;
    }
}

// ---------------------------------------------------------------------------
// Launch
// ---------------------------------------------------------------------------
extern "C" void kernel_launch(void* const* d_in, const int* in_sizes, int n_in,
                              void* d_out, int out_size)
{
    const float* query = (const float*)d_in[0];
    const float* key   = (const float*)d_in[1];
    const float* value = (const float*)d_in[2];
    const int*   mask  = (const int*)d_in[3];
    const float* Wq = (const float*)d_in[4];
    const float* bq = (const float*)d_in[5];
    const float* Wk = (const float*)d_in[6];
    const float* bk = (const float*)d_in[7];
    const float* Wv = (const float*)d_in[8];
    const float* bv = (const float*)d_in[9];
    const float* Wo = (const float*)d_in[10];
    const float* bo = (const float*)d_in[11];
    float* out = (float*)d_out;

    __nv_bfloat16 *pQh, *pQl, *pKh, *pKl, *pVh, *pVl, *pXh, *pXl, *pWh, *pWl;
    cudaGetSymbolAddress((void**)&pQh, g_Qh); cudaGetSymbolAddress((void**)&pQl, g_Ql);
    cudaGetSymbolAddress((void**)&pKh, g_Kh); cudaGetSymbolAddress((void**)&pKl, g_Kl);
    cudaGetSymbolAddress((void**)&pVh, g_Vh); cudaGetSymbolAddress((void**)&pVl, g_Vl);
    cudaGetSymbolAddress((void**)&pXh, g_Xh); cudaGetSymbolAddress((void**)&pXl, g_Xl);
    cudaGetSymbolAddress((void**)&pWh, g_Wh); cudaGetSymbolAddress((void**)&pWl, g_Wl);

    cudaFuncSetAttribute(gemm_bf16,
                         cudaFuncAttributeMaxDynamicSharedMemorySize, GEMM_SMEM);
    cudaFuncSetAttribute(attn_hmma,
                         cudaFuncAttributeMaxDynamicSharedMemorySize, ATTN_SMEM);

    const int nX4 = Mc * Dc / 4, nW4 = Dc * Dc / 4;
    const dim3 gg(Dc / 128, Mc / 128);

    // Q projection (scale 1/8 folded in)
    split_kernel<<<nX4 / 256, 256>>>(query, pXh, pXl, nX4);
    split_kernel<<<nW4 / 256, 256>>>(Wq, pWh, pWl, nW4);
    gemm_bf16<<<gg, 256, GEMM_SMEM>>>(pXh, pXl, pWh, pWl, bq, 0.125f,
                                      nullptr, pQh, pQl, 1);
    // K projection
    split_kernel<<<nX4 / 256, 256>>>(key, pXh, pXl, nX4);
    split_kernel<<<nW4 / 256, 256>>>(Wk, pWh, pWl, nW4);
    gemm_bf16<<<gg, 256, GEMM_SMEM>>>(pXh, pXl, pWh, pWl, bk, 1.0f,
                                      nullptr, pKh, pKl, 1);
    // V projection
    split_kernel<<<nX4 / 256, 256>>>(value, pXh, pXl, nX4);
    split_kernel<<<nW4 / 256, 256>>>(Wv, pWh, pWl, nW4);
    gemm_bf16<<<gg, 256, GEMM_SMEM>>>(pXh, pXl, pWh, pWl, bv, 1.0f,
                                      nullptr, pVh, pVl, 1);
    // Attention (writes ctx split into pXh/pXl)
    attn_hmma<<<dim3(Sc / 64, Hc, Bc), 128, ATTN_SMEM>>>(mask);
    // Output projection
    split_kernel<<<nW4 / 256, 256>>>(Wo, pWh, pWl, nW4);
    gemm_bf16<<<gg, 256, GEMM_SMEM>>>(pXh, pXl, pWh, pWl, bo, 1.0f,
                                      out, nullptr, nullptr, 0);
}

// round 8
// speedup vs baseline: 4.2447x; 1.5326x over previous
#include <cuda_runtime.h>
#include <cuda_fp16.h>
#include <math.h>
#include <stdint.h>

constexpr int Bc = 4;
constexpr int Sc = 2048;
constexpr int Dc = 1024;
constexpr int Hc = 16;
constexpr int DKc = 64;
constexpr int Mc = Bc * Sc;   // 8192

// fp16 buffers: split (hi+lo) for the exact operand, single for the rounded one
__device__ __half g_Qh[Mc * Dc], g_Ql[Mc * Dc];   // Q split (scaled 1/8)
__device__ __half g_Kh[Mc * Dc];                  // K single
__device__ __half g_Vh[Mc * Dc];                  // V single
__device__ __half g_Xh[Mc * Dc], g_Xl[Mc * Dc];   // GEMM A input / ctx split
__device__ __half g_Wh[Dc * Dc];                  // weight single
__device__ uint32_t g_mp[Bc * Sc * (Sc / 32)];    // packed mask bits

// ---------------------------------------------------------------------------
// Helpers
// ---------------------------------------------------------------------------
__device__ __forceinline__ uint32_t smem_u32(const void* p) {
    return (uint32_t)__cvta_generic_to_shared(p);
}
__device__ __forceinline__ void cp16(uint32_t dst, const void* src) {
    asm volatile("cp.async.cg.shared.global [%0], [%1], 16;" :: "r"(dst), "l"(src));
}
__device__ __forceinline__ void cp_commit() { asm volatile("cp.async.commit_group;"); }
template<int N> __device__ __forceinline__ void cp_wait() {
    asm volatile("cp.async.wait_group %0;" :: "n"(N));
}
__device__ __forceinline__ void ldsm4(uint32_t* r, uint32_t a) {
    asm volatile("ldmatrix.sync.aligned.m8n8.x4.shared.b16 {%0,%1,%2,%3}, [%4];"
        : "=r"(r[0]), "=r"(r[1]), "=r"(r[2]), "=r"(r[3]) : "r"(a));
}
__device__ __forceinline__ void ldsm4t(uint32_t* r, uint32_t a) {
    asm volatile("ldmatrix.sync.aligned.m8n8.x4.trans.shared.b16 {%0,%1,%2,%3}, [%4];"
        : "=r"(r[0]), "=r"(r[1]), "=r"(r[2]), "=r"(r[3]) : "r"(a));
}
__device__ __forceinline__ void mma16816(float* c, const uint32_t* a, const uint32_t* b) {
    asm volatile(
        "mma.sync.aligned.m16n8k16.row.col.f32.f16.f16.f32 "
        "{%0,%1,%2,%3}, {%4,%5,%6,%7}, {%8,%9}, {%0,%1,%2,%3};"
        : "+f"(c[0]), "+f"(c[1]), "+f"(c[2]), "+f"(c[3])
        : "r"(a[0]), "r"(a[1]), "r"(a[2]), "r"(a[3]), "r"(b[0]), "r"(b[1]));
}
// split (a,b) into packed fp16x2 hi + lo. low 16 bits = a (even col).
__device__ __forceinline__ uint32_t split_pack_h(float a, float b, uint32_t& lo) {
    __half2 h = __floats2half2_rn(a, b);
    float2 hf = __half22float2(h);
    __half2 l = __floats2half2_rn(a - hf.x, b - hf.y);
    lo = *reinterpret_cast<uint32_t*>(&l);
    return *reinterpret_cast<uint32_t*>(&h);
}
// swizzle for 128B-row tiles (8 x 16B chunks)
__device__ __forceinline__ uint32_t swz(int row, int ch) {
    return (uint32_t)((row << 7) + (((ch ^ row) & 7) << 4) + ((ch & ~7) << 4));
}
// swizzle for 64B-row tiles (4 x 16B chunks)
__device__ __forceinline__ uint32_t swz64(int row, int ch) {
    return (uint32_t)((row << 6) + (((ch ^ (row >> 1)) & 3) << 4));
}

// ---------------------------------------------------------------------------
// fp32 -> fp16 hi(+lo) split
// ---------------------------------------------------------------------------
__global__ __launch_bounds__(256) void split_h(
    const float* __restrict__ x, __half* __restrict__ hi,
    __half* __restrict__ lo, int n4)
{
    int i = blockIdx.x * blockDim.x + threadIdx.x;
    if (i >= n4) return;
    float4 v = reinterpret_cast<const float4*>(x)[i];
    uint32_t l0, l1;
    uint32_t h0 = split_pack_h(v.x, v.y, l0);
    uint32_t h1 = split_pack_h(v.z, v.w, l1);
    uint2 H = {h0, h1};
    reinterpret_cast<uint2*>(hi)[i] = H;
    if (lo) {
        uint2 L = {l0, l1};
        reinterpret_cast<uint2*>(lo)[i] = L;
    }
}

// ---------------------------------------------------------------------------
// Pack mask ints into bits: bit i of word w = (mask[w*32+i] != 0)
// ---------------------------------------------------------------------------
__global__ __launch_bounds__(256) void mask_pack(
    const int* __restrict__ mask, uint32_t* __restrict__ mp)
{
    int w = blockIdx.x * blockDim.x + threadIdx.x;
    const int* src = mask + (size_t)w * 32;
    uint32_t bits = 0;
#pragma unroll
    for (int i = 0; i < 32; i += 4) {
        int4 v = *reinterpret_cast<const int4*>(src + i);
        bits |= (uint32_t)(v.x != 0) << i;
        bits |= (uint32_t)(v.y != 0) << (i + 1);
        bits |= (uint32_t)(v.z != 0) << (i + 2);
        bits |= (uint32_t)(v.w != 0) << (i + 3);
    }
    mp[w] = bits;
}

// ---------------------------------------------------------------------------
// fp16 GEMM:  Y[m,n] = sum_k A[m,k]*B[n,k] + bias[n];  A exact (hi+lo), B single.
// Tile 128x128, k-chunk 32, 3-stage cp.async ring (one sync/iter), 2 CTA/SM.
// mode 0: fp32 flat out. mode 1: fp16 hi(+lo) out, head layout, *scale.
// ---------------------------------------------------------------------------
constexpr int GST = 24576;            // stage: Ah(8K) + Al(8K) + Bh(8K)
constexpr int GEMM_SMEM = 3 * GST;    // 72KB

__global__ __launch_bounds__(256, 2) void gemm_h(
    const __half* __restrict__ Ah, const __half* __restrict__ Al,
    const __half* __restrict__ Bh, const float* __restrict__ bias, float scale,
    float* __restrict__ Yf, __half* __restrict__ Yh, __half* __restrict__ Yl,
    int mode)
{
    extern __shared__ char smem[];
    const uint32_t sb = smem_u32(smem);
    const int t = threadIdx.x, wid = t >> 5, l = t & 31;
    const int g = l >> 2, tq = l & 3;
    const int n0 = blockIdx.x * 128, m0 = blockIdx.y * 128;
    const int mrow = (wid & 1) * 64, ncol = (wid >> 1) * 32;

    auto ld_stage = [&](int c, int s) {
        const uint32_t st = sb + (uint32_t)s * GST;
#pragma unroll
        for (int rep = 0; rep < 2; rep++) {
            const int id = t + 256 * rep;
            const int row = id >> 2, ch = id & 3;
            const int gk = c * 32 + ch * 8;
            const uint32_t d = swz64(row, ch);
            cp16(st + d,          Ah + (size_t)(m0 + row) * Dc + gk);
            cp16(st + 8192 + d,   Al + (size_t)(m0 + row) * Dc + gk);
            cp16(st + 16384 + d,  Bh + (size_t)(n0 + row) * Dc + gk);
        }
    };

    float acc[4][4][4];
#pragma unroll
    for (int i = 0; i < 4; i++)
#pragma unroll
        for (int j = 0; j < 4; j++)
#pragma unroll
            for (int k = 0; k < 4; k++) acc[i][j][k] = 0.f;

    ld_stage(0, 0); cp_commit();
    ld_stage(1, 1); cp_commit();

    const int arow = mrow + (l & 15);
    const int acs = l >> 4;
    const int brow = ncol + ((l >> 4) << 3) + (l & 7);
    const int bcs = (l >> 3) & 1;

    for (int c = 0; c < 32; c++) {
        if (c < 31) cp_wait<1>(); else cp_wait<0>();
        __syncthreads();
        if (c + 2 < 32) { ld_stage(c + 2, (c + 2) % 3); cp_commit(); }

        const uint32_t st = sb + (uint32_t)(c % 3) * GST;
#pragma unroll
        for (int ks = 0; ks < 2; ks++) {
            uint32_t bH[2][4];
#pragma unroll
            for (int jp = 0; jp < 2; jp++)
                ldsm4(bH[jp], st + 16384 + swz64(brow + 16 * jp, ks * 2 + bcs));
#pragma unroll
            for (int i = 0; i < 4; i++) {
                const uint32_t ad = swz64(arow + 16 * i, ks * 2 + acs);
                uint32_t aH[4], aL[4];
                ldsm4(aH, st + ad);
                ldsm4(aL, st + 8192 + ad);
#pragma unroll
                for (int jp = 0; jp < 2; jp++) {
                    mma16816(acc[i][2 * jp], aH, &bH[jp][0]);
                    mma16816(acc[i][2 * jp], aL, &bH[jp][0]);
                    mma16816(acc[i][2 * jp + 1], aH, &bH[jp][2]);
                    mma16816(acc[i][2 * jp + 1], aL, &bH[jp][2]);
                }
            }
        }
    }

    // Epilogue
#pragma unroll
    for (int i = 0; i < 4; i++) {
        const int m1 = m0 + mrow + 16 * i + g;
        const int m2 = m1 + 8;
#pragma unroll
        for (int j = 0; j < 4; j++) {
            const int nc = n0 + ncol + 8 * j + 2 * tq;
            const float2 bb = *reinterpret_cast<const float2*>(bias + nc);
            float v00 = acc[i][j][0] + bb.x, v01 = acc[i][j][1] + bb.y;
            float v10 = acc[i][j][2] + bb.x, v11 = acc[i][j][3] + bb.y;
            if (mode == 0) {
                float2 r0 = {v00, v01}, r1 = {v10, v11};
                *reinterpret_cast<float2*>(Yf + (size_t)m1 * Dc + nc) = r0;
                *reinterpret_cast<float2*>(Yf + (size_t)m2 * Dc + nc) = r1;
            } else {
                v00 *= scale; v01 *= scale; v10 *= scale; v11 *= scale;
                const int hh = nc >> 6, cc = nc & 63;
                uint32_t lo;
                {
                    const int bb2 = m1 >> 11, ss = m1 & (Sc - 1);
                    const size_t idx = (((size_t)(bb2 * Hc + hh) * Sc + ss) << 6) + cc;
                    uint32_t hi = split_pack_h(v00, v01, lo);
                    *reinterpret_cast<uint32_t*>(Yh + idx) = hi;
                    if (Yl) *reinterpret_cast<uint32_t*>(Yl + idx) = lo;
                }
                {
                    const int bb2 = m2 >> 11, ss = m2 & (Sc - 1);
                    const size_t idx = (((size_t)(bb2 * Hc + hh) * Sc + ss) << 6) + cc;
                    uint32_t hi = split_pack_h(v10, v11, lo);
                    *reinterpret_cast<uint32_t*>(Yh + idx) = hi;
                    if (Yl) *reinterpret_cast<uint32_t*>(Yl + idx) = lo;
                }
            }
        }
    }
}

// ---------------------------------------------------------------------------
// Flash attention (fp16 HMMA). CTA: 64 q-rows, 128 threads, 3 CTA/SM.
// QK^T: (Qh+Ql)*Kh (Q pre-scaled 1/8). PV: (Ph+Pl)*Vh.
// smem: Qh,Ql (8KB each) + 3 stages x (Kh,Vh; 8KB each) = 64KB.
// ---------------------------------------------------------------------------
constexpr int ATTN_SMEM = 16384 + 3 * 16384;

__global__ __launch_bounds__(128, 3) void attn_h()
{
    extern __shared__ char smem[];
    const uint32_t sb = smem_u32(smem);
    const int t = threadIdx.x, w = t >> 5, l = t & 31;
    const int g = l >> 2, tq = l & 3;
    const int q0 = blockIdx.x * 64;
    const int h = blockIdx.y, b = blockIdx.z;

    const size_t hb = (size_t)(b * Hc + h) * Sc * DKc;
    const __half* Qhg = g_Qh + hb + (size_t)q0 * DKc;
    const __half* Qlg = g_Ql + hb + (size_t)q0 * DKc;
    const __half* Khg = g_Kh + hb;
    const __half* Vhg = g_Vh + hb;

    const uint32_t QH = sb, QL = sb + 8192;

    auto ld_kv = [&](int jb, int s) {
        const uint32_t st = sb + 16384 + (uint32_t)s * 16384;
        const int k0 = jb * 64;
#pragma unroll
        for (int rep = 0; rep < 4; rep++) {
            const int id = t + 128 * rep;
            const int row = id >> 3, ch = id & 7;
            const size_t off = (size_t)(k0 + row) * DKc + ch * 8;
            const uint32_t d = swz(row, ch);
            cp16(st + d,         Khg + off);
            cp16(st + 8192 + d,  Vhg + off);
        }
    };

    // Q + first KV stage
    {
#pragma unroll
        for (int rep = 0; rep < 4; rep++) {
            const int id = t + 128 * rep;
            const int row = id >> 3, ch = id & 7;
            const size_t off = (size_t)row * DKc + ch * 8;
            const uint32_t d = swz(row, ch);
            cp16(QH + d, Qhg + off);
            cp16(QL + d, Qlg + off);
        }
        ld_kv(0, 0); cp_commit();
        ld_kv(1, 1); cp_commit();
    }

    float o[8][4];
#pragma unroll
    for (int j = 0; j < 8; j++)
#pragma unroll
        for (int k = 0; k < 4; k++) o[j][k] = 0.f;
    float m0 = -INFINITY, m1 = -INFINITY, l0 = 0.f, l1 = 0.f;

    const int qrow = q0 + 16 * w + g;
    const uint32_t* mp0 = g_mp + ((size_t)(b * Sc + qrow) << 6);  // 64 words/row
    const uint32_t* mp1 = mp0 + (8 << 6);

    const int arow = 16 * w + (l & 15);
    const int acs = l >> 4;
    const int brlo = ((l >> 4) << 3) + (l & 7);
    const int bcs = (l >> 3) & 1;
    const int vrlo = ((l >> 3) & 1) * 8 + (l & 7);
    const int vcs = (l >> 4) & 1;

    for (int jb = 0; jb < 32; jb++) {
        if (jb < 31) cp_wait<1>(); else cp_wait<0>();
        __syncthreads();
        if (jb + 2 < 32) { ld_kv(jb + 2, (jb + 2) % 3); cp_commit(); }

        const uint32_t st = sb + 16384 + (uint32_t)(jb % 3) * 16384;

        // --- S = Q K^T ---
        float sfr[8][4];
#pragma unroll
        for (int j = 0; j < 8; j++)
#pragma unroll
            for (int k = 0; k < 4; k++) sfr[j][k] = 0.f;

#pragma unroll
        for (int ks = 0; ks < 4; ks++) {
            uint32_t aH[4], aL[4];
            const uint32_t ad = swz(arow, ks * 2 + acs);
            ldsm4(aH, QH + ad);
            ldsm4(aL, QL + ad);
#pragma unroll
            for (int jp = 0; jp < 4; jp++) {
                uint32_t bH[4];
                ldsm4(bH, st + swz(16 * jp + brlo, ks * 2 + bcs));
                mma16816(sfr[2 * jp],     aH, &bH[0]);
                mma16816(sfr[2 * jp],     aL, &bH[0]);
                mma16816(sfr[2 * jp + 1], aH, &bH[2]);
                mma16816(sfr[2 * jp + 1], aL, &bH[2]);
            }
        }

        // --- mask (packed bits) + online softmax ---
        const uint2 w0 = *reinterpret_cast<const uint2*>(mp0 + jb * 2);
        const uint2 w1 = *reinterpret_cast<const uint2*>(mp1 + jb * 2);
#pragma unroll
        for (int j = 0; j < 8; j++) {
            const int bit = 8 * (j & 3) + 2 * tq;
            const uint32_t wa = (j < 4) ? w0.x : w0.y;
            const uint32_t wb = (j < 4) ? w1.x : w1.y;
            sfr[j][0] = ((wa >> bit) & 1)       ? sfr[j][0] : -1e9f;
            sfr[j][1] = ((wa >> (bit + 1)) & 1) ? sfr[j][1] : -1e9f;
            sfr[j][2] = ((wb >> bit) & 1)       ? sfr[j][2] : -1e9f;
            sfr[j][3] = ((wb >> (bit + 1)) & 1) ? sfr[j][3] : -1e9f;
        }
        float mx0 = -INFINITY, mx1 = -INFINITY;
#pragma unroll
        for (int j = 0; j < 8; j++) {
            mx0 = fmaxf(mx0, fmaxf(sfr[j][0], sfr[j][1]));
            mx1 = fmaxf(mx1, fmaxf(sfr[j][2], sfr[j][3]));
        }
        mx0 = fmaxf(mx0, __shfl_xor_sync(0xffffffffu, mx0, 1));
        mx0 = fmaxf(mx0, __shfl_xor_sync(0xffffffffu, mx0, 2));
        mx1 = fmaxf(mx1, __shfl_xor_sync(0xffffffffu, mx1, 1));
        mx1 = fmaxf(mx1, __shfl_xor_sync(0xffffffffu, mx1, 2));
        const float mn0 = fmaxf(m0, mx0), mn1 = fmaxf(m1, mx1);
        const float cr0 = __expf(m0 - mn0), cr1 = __expf(m1 - mn1);
        float s0 = 0.f, s1 = 0.f;
#pragma unroll
        for (int j = 0; j < 8; j++) {
            sfr[j][0] = __expf(sfr[j][0] - mn0); s0 += sfr[j][0];
            sfr[j][1] = __expf(sfr[j][1] - mn0); s0 += sfr[j][1];
            sfr[j][2] = __expf(sfr[j][2] - mn1); s1 += sfr[j][2];
            sfr[j][3] = __expf(sfr[j][3] - mn1); s1 += sfr[j][3];
        }
        s0 += __shfl_xor_sync(0xffffffffu, s0, 1);
        s0 += __shfl_xor_sync(0xffffffffu, s0, 2);
        s1 += __shfl_xor_sync(0xffffffffu, s1, 1);
        s1 += __shfl_xor_sync(0xffffffffu, s1, 2);
        l0 = l0 * cr0 + s0;  m0 = mn0;
        l1 = l1 * cr1 + s1;  m1 = mn1;
#pragma unroll
        for (int j = 0; j < 8; j++) {
            o[j][0] *= cr0; o[j][1] *= cr0; o[j][2] *= cr1; o[j][3] *= cr1;
        }

        // --- O += P V ---
#pragma unroll
        for (int ks = 0; ks < 4; ks++) {
            uint32_t aPh[4], aPl[4];
            aPh[0] = split_pack_h(sfr[2 * ks][0],     sfr[2 * ks][1],     aPl[0]);
            aPh[1] = split_pack_h(sfr[2 * ks][2],     sfr[2 * ks][3],     aPl[1]);
            aPh[2] = split_pack_h(sfr[2 * ks + 1][0], sfr[2 * ks + 1][1], aPl[2]);
            aPh[3] = split_pack_h(sfr[2 * ks + 1][2], sfr[2 * ks + 1][3], aPl[3]);
#pragma unroll
            for (int jp = 0; jp < 4; jp++) {
                uint32_t vH[4];
                ldsm4t(vH, st + 8192 + swz(16 * ks + vrlo, 2 * jp + vcs));
                mma16816(o[2 * jp],     aPh, &vH[0]);
                mma16816(o[2 * jp],     aPl, &vH[0]);
                mma16816(o[2 * jp + 1], aPh, &vH[2]);
                mma16816(o[2 * jp + 1], aPl, &vH[2]);
            }
        }
    }

    // Epilogue: ctx written pre-split, flat [B*S, D]
    const float i0 = 1.f / l0, i1 = 1.f / l1;
    const size_t r0 = (size_t)(b * Sc + qrow) * Dc + h * DKc;
    const size_t r1 = r0 + 8 * Dc;
#pragma unroll
    for (int j = 0; j < 8; j++) {
        const int cc = 8 * j + 2 * tq;
        uint32_t lo;
        uint32_t hi = split_pack_h(o[j][0] * i0, o[j][1] * i0, lo);
        *reinterpret_cast<uint32_t*>(g_Xh + r0 + cc) = hi;
        *reinterpret_cast<uint32_t*>(g_Xl + r0 + cc) = lo;
        hi = split_pack_h(o[j][2] * i1, o[j][3] * i1, lo);
        *reinterpret_cast<uint32_t*>(g_Xh + r1 + cc) = hi;
        *reinterpret_cast<uint32_t*>(g_Xl + r1 + cc) = lo;
    }
}

// ---------------------------------------------------------------------------
// Launch
// ---------------------------------------------------------------------------
extern "C" void kernel_launch(void* const* d_in, const int* in_sizes, int n_in,
                              void* d_out, int out_size)
{
    const float* query = (const float*)d_in[0];
    const float* key   = (const float*)d_in[1];
    const float* value = (const float*)d_in[2];
    const int*   mask  = (const int*)d_in[3];
    const float* Wq = (const float*)d_in[4];
    const float* bq = (const float*)d_in[5];
    const float* Wk = (const float*)d_in[6];
    const float* bk = (const float*)d_in[7];
    const float* Wv = (const float*)d_in[8];
    const float* bv = (const float*)d_in[9];
    const float* Wo = (const float*)d_in[10];
    const float* bo = (const float*)d_in[11];
    float* out = (float*)d_out;

    __half *pQh, *pQl, *pKh, *pVh, *pXh, *pXl, *pWh;
    uint32_t* pMp;
    cudaGetSymbolAddress((void**)&pQh, g_Qh);
    cudaGetSymbolAddress((void**)&pQl, g_Ql);
    cudaGetSymbolAddress((void**)&pKh, g_Kh);
    cudaGetSymbolAddress((void**)&pVh, g_Vh);
    cudaGetSymbolAddress((void**)&pXh, g_Xh);
    cudaGetSymbolAddress((void**)&pXl, g_Xl);
    cudaGetSymbolAddress((void**)&pWh, g_Wh);
    cudaGetSymbolAddress((void**)&pMp, g_mp);

    cudaFuncSetAttribute(gemm_h,
                         cudaFuncAttributeMaxDynamicSharedMemorySize, GEMM_SMEM);
    cudaFuncSetAttribute(attn_h,
                         cudaFuncAttributeMaxDynamicSharedMemorySize, ATTN_SMEM);

    const int nX4 = Mc * Dc / 4, nW4 = Dc * Dc / 4;
    const dim3 gg(Dc / 128, Mc / 128);

    // Q projection (scale 1/8 folded in, split output)
    split_h<<<nX4 / 256, 256>>>(query, pXh, pXl, nX4);
    split_h<<<nW4 / 256, 256>>>(Wq, pWh, nullptr, nW4);
    gemm_h<<<gg, 256, GEMM_SMEM>>>(pXh, pXl, pWh, bq, 0.125f,
                                   nullptr, pQh, pQl, 1);
    // K projection (single fp16 output)
    split_h<<<nX4 / 256, 256>>>(key, pXh, pXl, nX4);
    split_h<<<nW4 / 256, 256>>>(Wk, pWh, nullptr, nW4);
    gemm_h<<<gg, 256, GEMM_SMEM>>>(pXh, pXl, pWh, bk, 1.0f,
                                   nullptr, pKh, nullptr, 1);
    // V projection (single fp16 output)
    split_h<<<nX4 / 256, 256>>>(value, pXh, pXl, nX4);
    split_h<<<nW4 / 256, 256>>>(Wv, pWh, nullptr, nW4);
    gemm_h<<<gg, 256, GEMM_SMEM>>>(pXh, pXl, pWh, bv, 1.0f,
                                   nullptr, pVh, nullptr, 1);
    // Mask bit-pack
    mask_pack<<<Bc * Sc * (Sc / 32) / 256, 256>>>(mask, pMp);
    // Attention (writes ctx split into g_Xh/g_Xl)
    attn_h<<<dim3(Sc / 64, Hc, Bc), 128, ATTN_SMEM>>>();
    // Output projection
    split_h<<<nW4 / 256, 256>>>(Wo, pWh, nullptr, nW4);
    gemm_h<<<gg, 256, GEMM_SMEM>>>(pXh, pXl, pWh, bo, 1.0f,
                                   out, nullptr, nullptr, 0);
}

// round 9
// speedup vs baseline: 6.7170x; 1.5824x over previous
#include <cuda_runtime.h>
#include <cuda_fp16.h>
#include <math.h>
#include <stdint.h>

constexpr int Bc = 4;
constexpr int Sc = 2048;
constexpr int Dc = 1024;
constexpr int Hc = 16;
constexpr int DKc = 64;
constexpr int Mc = Bc * Sc;   // 8192

// fp16 buffers (single precision-rounded operands everywhere)
__device__ __half g_Q[Mc * Dc];                 // Q (scaled 1/8), head layout
__device__ __half g_K[Mc * Dc];                 // K, head layout
__device__ __half g_V[Mc * Dc];                 // V, head layout
__device__ __half g_X[Mc * Dc];                 // GEMM A input / ctx, flat
__device__ __half g_W[Dc * Dc];                 // weight (reused per GEMM)
__device__ uint32_t g_mp[Bc * Sc * (Sc / 32)];  // packed mask bits

// ---------------------------------------------------------------------------
// Helpers
// ---------------------------------------------------------------------------
__device__ __forceinline__ uint32_t smem_u32(const void* p) {
    return (uint32_t)__cvta_generic_to_shared(p);
}
__device__ __forceinline__ void cp16(uint32_t dst, const void* src) {
    asm volatile("cp.async.cg.shared.global [%0], [%1], 16;" :: "r"(dst), "l"(src));
}
__device__ __forceinline__ void cp_commit() { asm volatile("cp.async.commit_group;"); }
template<int N> __device__ __forceinline__ void cp_wait() {
    asm volatile("cp.async.wait_group %0;" :: "n"(N));
}
__device__ __forceinline__ void ldsm4(uint32_t* r, uint32_t a) {
    asm volatile("ldmatrix.sync.aligned.m8n8.x4.shared.b16 {%0,%1,%2,%3}, [%4];"
        : "=r"(r[0]), "=r"(r[1]), "=r"(r[2]), "=r"(r[3]) : "r"(a));
}
__device__ __forceinline__ void ldsm4t(uint32_t* r, uint32_t a) {
    asm volatile("ldmatrix.sync.aligned.m8n8.x4.trans.shared.b16 {%0,%1,%2,%3}, [%4];"
        : "=r"(r[0]), "=r"(r[1]), "=r"(r[2]), "=r"(r[3]) : "r"(a));
}
__device__ __forceinline__ void mma16816(float* c, const uint32_t* a, const uint32_t* b) {
    asm volatile(
        "mma.sync.aligned.m16n8k16.row.col.f32.f16.f16.f32 "
        "{%0,%1,%2,%3}, {%4,%5,%6,%7}, {%8,%9}, {%0,%1,%2,%3};"
        : "+f"(c[0]), "+f"(c[1]), "+f"(c[2]), "+f"(c[3])
        : "r"(a[0]), "r"(a[1]), "r"(a[2]), "r"(a[3]), "r"(b[0]), "r"(b[1]));
}
__device__ __forceinline__ uint32_t pack_h2(float a, float b) {
    __half2 h = __floats2half2_rn(a, b);
    return *reinterpret_cast<uint32_t*>(&h);
}
// swizzle for 128B-row tiles (8 x 16B chunks per row)
__device__ __forceinline__ uint32_t swz(int row, int ch) {
    return (uint32_t)((row << 7) + (((ch ^ row) & 7) << 4) + ((ch & ~7) << 4));
}

// ---------------------------------------------------------------------------
// fp32 -> fp16 convert
// ---------------------------------------------------------------------------
__global__ __launch_bounds__(256) void cvt_h(
    const float* __restrict__ x, __half* __restrict__ y, int n4)
{
    int i = blockIdx.x * blockDim.x + threadIdx.x;
    if (i >= n4) return;
    float4 v = reinterpret_cast<const float4*>(x)[i];
    uint2 H = {pack_h2(v.x, v.y), pack_h2(v.z, v.w)};
    reinterpret_cast<uint2*>(y)[i] = H;
}

// ---------------------------------------------------------------------------
// Pack mask ints into bits
// ---------------------------------------------------------------------------
__global__ __launch_bounds__(256) void mask_pack(
    const int* __restrict__ mask, uint32_t* __restrict__ mp)
{
    int w = blockIdx.x * blockDim.x + threadIdx.x;
    const int* src = mask + (size_t)w * 32;
    uint32_t bits = 0;
#pragma unroll
    for (int i = 0; i < 32; i += 4) {
        int4 v = *reinterpret_cast<const int4*>(src + i);
        bits |= (uint32_t)(v.x != 0) << i;
        bits |= (uint32_t)(v.y != 0) << (i + 1);
        bits |= (uint32_t)(v.z != 0) << (i + 2);
        bits |= (uint32_t)(v.w != 0) << (i + 3);
    }
    mp[w] = bits;
}

// ---------------------------------------------------------------------------
// fp16 GEMM:  Y[m,n] = sum_k A[m,k]*B[n,k] + bias[n]   (both operands fp16)
// Tile 128x128, k-chunk 64, 3-stage cp.async ring, 2 CTA/SM.
// mode 0: fp32 flat out. mode 1: fp16 out, head layout, *scale.
// ---------------------------------------------------------------------------
constexpr int GST = 32768;            // stage: A(16K) + B(16K)
constexpr int GEMM_SMEM = 3 * GST;    // 96KB

__global__ __launch_bounds__(256, 2) void gemm_h(
    const __half* __restrict__ A, const __half* __restrict__ B,
    const float* __restrict__ bias, float scale,
    float* __restrict__ Yf, __half* __restrict__ Yh, int mode)
{
    extern __shared__ char smem[];
    const uint32_t sb = smem_u32(smem);
    const int t = threadIdx.x, wid = t >> 5, l = t & 31;
    const int g = l >> 2, tq = l & 3;
    const int n0 = blockIdx.x * 128, m0 = blockIdx.y * 128;
    const int mrow = (wid & 1) * 64, ncol = (wid >> 1) * 32;

    auto ld_stage = [&](int c, int s) {
        const uint32_t st = sb + (uint32_t)s * GST;
#pragma unroll
        for (int rep = 0; rep < 4; rep++) {
            const int id = t + 256 * rep;
            const int row = id >> 3, ch = id & 7;
            const int gk = c * 64 + ch * 8;
            const uint32_t d = swz(row, ch);
            cp16(st + d,          A + (size_t)(m0 + row) * Dc + gk);
            cp16(st + 16384 + d,  B + (size_t)(n0 + row) * Dc + gk);
        }
    };

    float acc[4][4][4];
#pragma unroll
    for (int i = 0; i < 4; i++)
#pragma unroll
        for (int j = 0; j < 4; j++)
#pragma unroll
            for (int k = 0; k < 4; k++) acc[i][j][k] = 0.f;

    ld_stage(0, 0); cp_commit();
    ld_stage(1, 1); cp_commit();

    const int arow = mrow + (l & 15);
    const int acs = l >> 4;
    const int brow = ncol + ((l >> 4) << 3) + (l & 7);
    const int bcs = (l >> 3) & 1;

    for (int c = 0; c < 16; c++) {
        if (c < 15) cp_wait<1>(); else cp_wait<0>();
        __syncthreads();
        if (c + 2 < 16) { ld_stage(c + 2, (c + 2) % 3); cp_commit(); }

        const uint32_t st = sb + (uint32_t)(c % 3) * GST;
#pragma unroll
        for (int ks = 0; ks < 4; ks++) {
            uint32_t bH[2][4];
#pragma unroll
            for (int jp = 0; jp < 2; jp++)
                ldsm4(bH[jp], st + 16384 + swz(brow + 16 * jp, ks * 2 + bcs));
#pragma unroll
            for (int i = 0; i < 4; i++) {
                uint32_t aH[4];
                ldsm4(aH, st + swz(arow + 16 * i, ks * 2 + acs));
#pragma unroll
                for (int jp = 0; jp < 2; jp++) {
                    mma16816(acc[i][2 * jp],     aH, &bH[jp][0]);
                    mma16816(acc[i][2 * jp + 1], aH, &bH[jp][2]);
                }
            }
        }
    }

    // Epilogue
#pragma unroll
    for (int i = 0; i < 4; i++) {
        const int m1 = m0 + mrow + 16 * i + g;
        const int m2 = m1 + 8;
#pragma unroll
        for (int j = 0; j < 4; j++) {
            const int nc = n0 + ncol + 8 * j + 2 * tq;
            const float2 bb = *reinterpret_cast<const float2*>(bias + nc);
            float v00 = acc[i][j][0] + bb.x, v01 = acc[i][j][1] + bb.y;
            float v10 = acc[i][j][2] + bb.x, v11 = acc[i][j][3] + bb.y;
            if (mode == 0) {
                float2 r0 = {v00, v01}, r1 = {v10, v11};
                *reinterpret_cast<float2*>(Yf + (size_t)m1 * Dc + nc) = r0;
                *reinterpret_cast<float2*>(Yf + (size_t)m2 * Dc + nc) = r1;
            } else {
                const int hh = nc >> 6, cc = nc & 63;
                {
                    const int bb2 = m1 >> 11, ss = m1 & (Sc - 1);
                    const size_t idx = (((size_t)(bb2 * Hc + hh) * Sc + ss) << 6) + cc;
                    *reinterpret_cast<uint32_t*>(Yh + idx) =
                        pack_h2(v00 * scale, v01 * scale);
                }
                {
                    const int bb2 = m2 >> 11, ss = m2 & (Sc - 1);
                    const size_t idx = (((size_t)(bb2 * Hc + hh) * Sc + ss) << 6) + cc;
                    *reinterpret_cast<uint32_t*>(Yh + idx) =
                        pack_h2(v10 * scale, v11 * scale);
                }
            }
        }
    }
}

// ---------------------------------------------------------------------------
// Flash attention (fp16 HMMA, single-rounded operands).
// CTA: 64 q-rows, 128 threads, 4 CTA/SM.
// smem: Q (8KB) + 3 stages x (K,V; 8KB each) = 56KB.
// ---------------------------------------------------------------------------
constexpr int ATTN_SMEM = 8192 + 3 * 16384;

__global__ __launch_bounds__(128, 4) void attn_h()
{
    extern __shared__ char smem[];
    const uint32_t sb = smem_u32(smem);
    const int t = threadIdx.x, w = t >> 5, l = t & 31;
    const int g = l >> 2, tq = l & 3;
    const int q0 = blockIdx.x * 64;
    const int h = blockIdx.y, b = blockIdx.z;

    const size_t hb = (size_t)(b * Hc + h) * Sc * DKc;
    const __half* Qg = g_Q + hb + (size_t)q0 * DKc;
    const __half* Kg = g_K + hb;
    const __half* Vg = g_V + hb;

    const uint32_t QS = sb;

    auto ld_kv = [&](int jb, int s) {
        const uint32_t st = sb + 8192 + (uint32_t)s * 16384;
        const int k0 = jb * 64;
#pragma unroll
        for (int rep = 0; rep < 4; rep++) {
            const int id = t + 128 * rep;
            const int row = id >> 3, ch = id & 7;
            const size_t off = (size_t)(k0 + row) * DKc + ch * 8;
            const uint32_t d = swz(row, ch);
            cp16(st + d,         Kg + off);
            cp16(st + 8192 + d,  Vg + off);
        }
    };

    // Q + first KV stages
    {
#pragma unroll
        for (int rep = 0; rep < 4; rep++) {
            const int id = t + 128 * rep;
            const int row = id >> 3, ch = id & 7;
            if (rep < 2 || id < 512) { }
            if (id < 512) {
                const size_t off = (size_t)row * DKc + ch * 8;
                cp16(QS + swz(row, ch), Qg + off);
            }
        }
        ld_kv(0, 0); cp_commit();
        ld_kv(1, 1); cp_commit();
    }

    float o[8][4];
#pragma unroll
    for (int j = 0; j < 8; j++)
#pragma unroll
        for (int k = 0; k < 4; k++) o[j][k] = 0.f;
    float m0 = -INFINITY, m1 = -INFINITY, l0 = 0.f, l1 = 0.f;

    const int qrow = q0 + 16 * w + g;
    const uint32_t* mp0 = g_mp + ((size_t)(b * Sc + qrow) << 6);  // 64 words/row
    const uint32_t* mp1 = mp0 + (8 << 6);

    const int arow = 16 * w + (l & 15);
    const int acs = l >> 4;
    const int brlo = ((l >> 4) << 3) + (l & 7);
    const int bcs = (l >> 3) & 1;
    const int vrlo = ((l >> 3) & 1) * 8 + (l & 7);
    const int vcs = (l >> 4) & 1;

    for (int jb = 0; jb < 32; jb++) {
        if (jb < 31) cp_wait<1>(); else cp_wait<0>();
        __syncthreads();
        if (jb + 2 < 32) { ld_kv(jb + 2, (jb + 2) % 3); cp_commit(); }

        const uint32_t st = sb + 8192 + (uint32_t)(jb % 3) * 16384;

        // --- S = Q K^T ---
        float sfr[8][4];
#pragma unroll
        for (int j = 0; j < 8; j++)
#pragma unroll
            for (int k = 0; k < 4; k++) sfr[j][k] = 0.f;

#pragma unroll
        for (int ks = 0; ks < 4; ks++) {
            uint32_t aH[4];
            ldsm4(aH, QS + swz(arow, ks * 2 + acs));
#pragma unroll
            for (int jp = 0; jp < 4; jp++) {
                uint32_t bH[4];
                ldsm4(bH, st + swz(16 * jp + brlo, ks * 2 + bcs));
                mma16816(sfr[2 * jp],     aH, &bH[0]);
                mma16816(sfr[2 * jp + 1], aH, &bH[2]);
            }
        }

        // --- mask (packed bits) + online softmax ---
        const uint2 w0 = *reinterpret_cast<const uint2*>(mp0 + jb * 2);
        const uint2 w1 = *reinterpret_cast<const uint2*>(mp1 + jb * 2);
#pragma unroll
        for (int j = 0; j < 8; j++) {
            const int bit = 8 * (j & 3) + 2 * tq;
            const uint32_t wa = (j < 4) ? w0.x : w0.y;
            const uint32_t wb = (j < 4) ? w1.x : w1.y;
            sfr[j][0] = ((wa >> bit) & 1)       ? sfr[j][0] : -1e9f;
            sfr[j][1] = ((wa >> (bit + 1)) & 1) ? sfr[j][1] : -1e9f;
            sfr[j][2] = ((wb >> bit) & 1)       ? sfr[j][2] : -1e9f;
            sfr[j][3] = ((wb >> (bit + 1)) & 1) ? sfr[j][3] : -1e9f;
        }
        float mx0 = -INFINITY, mx1 = -INFINITY;
#pragma unroll
        for (int j = 0; j < 8; j++) {
            mx0 = fmaxf(mx0, fmaxf(sfr[j][0], sfr[j][1]));
            mx1 = fmaxf(mx1, fmaxf(sfr[j][2], sfr[j][3]));
        }
        mx0 = fmaxf(mx0, __shfl_xor_sync(0xffffffffu, mx0, 1));
        mx0 = fmaxf(mx0, __shfl_xor_sync(0xffffffffu, mx0, 2));
        mx1 = fmaxf(mx1, __shfl_xor_sync(0xffffffffu, mx1, 1));
        mx1 = fmaxf(mx1, __shfl_xor_sync(0xffffffffu, mx1, 2));
        const float mn0 = fmaxf(m0, mx0), mn1 = fmaxf(m1, mx1);
        const float cr0 = __expf(m0 - mn0), cr1 = __expf(m1 - mn1);
        float s0 = 0.f, s1 = 0.f;
#pragma unroll
        for (int j = 0; j < 8; j++) {
            sfr[j][0] = __expf(sfr[j][0] - mn0); s0 += sfr[j][0];
            sfr[j][1] = __expf(sfr[j][1] - mn0); s0 += sfr[j][1];
            sfr[j][2] = __expf(sfr[j][2] - mn1); s1 += sfr[j][2];
            sfr[j][3] = __expf(sfr[j][3] - mn1); s1 += sfr[j][3];
        }
        s0 += __shfl_xor_sync(0xffffffffu, s0, 1);
        s0 += __shfl_xor_sync(0xffffffffu, s0, 2);
        s1 += __shfl_xor_sync(0xffffffffu, s1, 1);
        s1 += __shfl_xor_sync(0xffffffffu, s1, 2);
        l0 = l0 * cr0 + s0;  m0 = mn0;
        l1 = l1 * cr1 + s1;  m1 = mn1;
#pragma unroll
        for (int j = 0; j < 8; j++) {
            o[j][0] *= cr0; o[j][1] *= cr0; o[j][2] *= cr1; o[j][3] *= cr1;
        }

        // --- O += P V ---
#pragma unroll
        for (int ks = 0; ks < 4; ks++) {
            uint32_t aP[4];
            aP[0] = pack_h2(sfr[2 * ks][0],     sfr[2 * ks][1]);
            aP[1] = pack_h2(sfr[2 * ks][2],     sfr[2 * ks][3]);
            aP[2] = pack_h2(sfr[2 * ks + 1][0], sfr[2 * ks + 1][1]);
            aP[3] = pack_h2(sfr[2 * ks + 1][2], sfr[2 * ks + 1][3]);
#pragma unroll
            for (int jp = 0; jp < 4; jp++) {
                uint32_t vH[4];
                ldsm4t(vH, st + 8192 + swz(16 * ks + vrlo, 2 * jp + vcs));
                mma16816(o[2 * jp],     aP, &vH[0]);
                mma16816(o[2 * jp + 1], aP, &vH[2]);
            }
        }
    }

    // Epilogue: ctx written fp16, flat [B*S, D]
    const float i0 = 1.f / l0, i1 = 1.f / l1;
    const size_t r0 = (size_t)(b * Sc + qrow) * Dc + h * DKc;
    const size_t r1 = r0 + 8 * Dc;
#pragma unroll
    for (int j = 0; j < 8; j++) {
        const int cc = 8 * j + 2 * tq;
        *reinterpret_cast<uint32_t*>(g_X + r0 + cc) =
            pack_h2(o[j][0] * i0, o[j][1] * i0);
        *reinterpret_cast<uint32_t*>(g_X + r1 + cc) =
            pack_h2(o[j][2] * i1, o[j][3] * i1);
    }
}

// ---------------------------------------------------------------------------
// Launch
// ---------------------------------------------------------------------------
extern "C" void kernel_launch(void* const* d_in, const int* in_sizes, int n_in,
                              void* d_out, int out_size)
{
    const float* query = (const float*)d_in[0];
    const float* key   = (const float*)d_in[1];
    const float* value = (const float*)d_in[2];
    const int*   mask  = (const int*)d_in[3];
    const float* Wq = (const float*)d_in[4];
    const float* bq = (const float*)d_in[5];
    const float* Wk = (const float*)d_in[6];
    const float* bk = (const float*)d_in[7];
    const float* Wv = (const float*)d_in[8];
    const float* bv = (const float*)d_in[9];
    const float* Wo = (const float*)d_in[10];
    const float* bo = (const float*)d_in[11];
    float* out = (float*)d_out;

    __half *pQ, *pK, *pV, *pX, *pW;
    uint32_t* pMp;
    cudaGetSymbolAddress((void**)&pQ, g_Q);
    cudaGetSymbolAddress((void**)&pK, g_K);
    cudaGetSymbolAddress((void**)&pV, g_V);
    cudaGetSymbolAddress((void**)&pX, g_X);
    cudaGetSymbolAddress((void**)&pW, g_W);
    cudaGetSymbolAddress((void**)&pMp, g_mp);

    cudaFuncSetAttribute(gemm_h,
                         cudaFuncAttributeMaxDynamicSharedMemorySize, GEMM_SMEM);
    cudaFuncSetAttribute(attn_h,
                         cudaFuncAttributeMaxDynamicSharedMemorySize, ATTN_SMEM);

    const int nX4 = Mc * Dc / 4, nW4 = Dc * Dc / 4;
    const dim3 gg(Dc / 128, Mc / 128);

    // Q projection (scale 1/8 folded in)
    cvt_h<<<nX4 / 256, 256>>>(query, pX, nX4);
    cvt_h<<<nW4 / 256, 256>>>(Wq, pW, nW4);
    gemm_h<<<gg, 256, GEMM_SMEM>>>(pX, pW, bq, 0.125f, nullptr, pQ, 1);
    // K projection
    cvt_h<<<nX4 / 256, 256>>>(key, pX, nX4);
    cvt_h<<<nW4 / 256, 256>>>(Wk, pW, nW4);
    gemm_h<<<gg, 256, GEMM_SMEM>>>(pX, pW, bk, 1.0f, nullptr, pK, 1);
    // V projection
    cvt_h<<<nX4 / 256, 256>>>(value, pX, nX4);
    cvt_h<<<nW4 / 256, 256>>>(Wv, pW, nW4);
    gemm_h<<<gg, 256, GEMM_SMEM>>>(pX, pW, bv, 1.0f, nullptr, pV, 1);
    // Mask bit-pack
    mask_pack<<<Bc * Sc * (Sc / 32) / 256, 256>>>(mask, pMp);
    // Attention (writes ctx into g_X)
    attn_h<<<dim3(Sc / 64, Hc, Bc), 128, ATTN_SMEM>>>();
    // Output projection
    cvt_h<<<nW4 / 256, 256>>>(Wo, pW, nW4);
    gemm_h<<<gg, 256, GEMM_SMEM>>>(pX, pW, bo, 1.0f, out, nullptr, 0);
}